// round 10
// baseline (speedup 1.0000x reference)
#include <cuda_runtime.h>
#include <cuda_bf16.h>
#include <math.h>
#include <stdint.h>

#define B_ 16
#define T_ 256
#define S_ 1024
#define E_ 1024
#define V_ 32000
#define NBLK 148
#define RTHR 256                      // recurrence block size (reg headroom: 255/thread)
#define NC_ 16                        // K chunks of 64 (GEMM)
#define STAGE_BYTES 65536             // Ahi/Alo/Bhi/Blo, 16 KB each

typedef unsigned long long u64;

// ------------------ scratch (device globals; no allocation allowed) -------------
__device__ float g_Xemb[T_*B_*E_];      // embeddings; later reused as H1
__device__ float g_Xz0[T_*B_*S_];
__device__ float g_Xr0[T_*B_*S_];
__device__ float g_Xn0[T_*B_*S_];
__device__ float g_H2[T_*B_*S_];
__device__ float g_WhT[6*S_*S_];        // fp32 transposed hidden weights (recurrence)
__device__ float g_hb0[B_*S_];          // [c*16+b]
__device__ float g_hb1[B_*S_];
__device__ float g_zbuf[B_*S_];         // [c*16+b]
__device__ float g_rhbuf[B_*S_];        // [c*16+b]
__device__ unsigned int g_flags[256];
// bf16 split operands for tensor-core GEMMs
__device__ uint16_t g_Ahi[T_*B_*E_];
__device__ uint16_t g_Alo[T_*B_*E_];
__device__ uint16_t g_Whi[6*S_*S_ + V_*S_];
__device__ uint16_t g_Wlo[6*S_*S_ + V_*S_];

// ------------------ PTX helpers --------------------------------------------------
__device__ __forceinline__ uint32_t smem_u32(const void* p) {
    uint32_t a;
    asm("{ .reg .u64 t; cvta.to.shared.u64 t, %1; cvt.u32.u64 %0, t; }" : "=r"(a) : "l"(p));
    return a;
}
__device__ __forceinline__ void cpa16(uint32_t s, const void* g) {
    asm volatile("cp.async.cg.shared.global [%0], [%1], 16;" :: "r"(s), "l"(g));
}
__device__ __forceinline__ void cpa_commit() { asm volatile("cp.async.commit_group;"); }
template <int N> __device__ __forceinline__ void cpa_wait() {
    asm volatile("cp.async.wait_group %0;" :: "n"(N));
}
#define LDSM4(r0, r1, r2, r3, a) \
    asm volatile("ldmatrix.sync.aligned.m8n8.x4.shared.b16 {%0,%1,%2,%3}, [%4];" \
        : "=r"(r0), "=r"(r1), "=r"(r2), "=r"(r3) : "r"(a))
#define MMA16816(d, a, b) \
    asm volatile("mma.sync.aligned.m16n8k16.row.col.f32.bf16.bf16.f32 " \
        "{%0,%1,%2,%3}, {%4,%5,%6,%7}, {%8,%9}, {%0,%1,%2,%3};" \
        : "+f"((d)[0]), "+f"((d)[1]), "+f"((d)[2]), "+f"((d)[3]) \
        : "r"((a)[0]), "r"((a)[1]), "r"((a)[2]), "r"((a)[3]), "r"((b)[0]), "r"((b)[1]))

// packed f32x2 ops (baseline sm_100+, PTX-only)
__device__ __forceinline__ void fma2(u64& d, u64 a, u64 b) {
    asm("fma.rn.f32x2 %0, %1, %2, %0;" : "+l"(d) : "l"(a), "l"(b));
}
__device__ __forceinline__ u64 add2(u64 a, u64 b) {
    u64 r; asm("add.rn.f32x2 %0, %1, %2;" : "=l"(r) : "l"(a), "l"(b)); return r;
}
__device__ __forceinline__ u64 dup2(float v) {
    u64 r; asm("mov.b64 %0, {%1, %1};" : "=l"(r) : "f"(v)); return r;
}
__device__ __forceinline__ float2 unpack2(u64 v) {
    float2 r; asm("mov.b64 {%0, %1}, %2;" : "=f"(r.x), "=f"(r.y) : "l"(v)); return r;
}
__device__ __forceinline__ u64 shfl64(u64 v, int off) {
    return __shfl_xor_sync(0xffffffffu, v, off);
}

// ------------------ small utility kernels ---------------------------------------
__global__ void reset_k() { if (threadIdx.x < 256) g_flags[threadIdx.x] = 0u; }

__global__ void embed_k(const int* __restrict__ x, const float* __restrict__ emb) {
    int idx = blockIdx.x * blockDim.x + threadIdx.x;
    const int total = T_ * B_ * (E_ / 4);
    const int stride = gridDim.x * blockDim.x;
    for (; idx < total; idx += stride) {
        int e4 = idx & (E_/4 - 1);
        int tb = idx >> 8;
        int t = tb >> 4, b = tb & 15;
        int tok = x[b * T_ + t];
        reinterpret_cast<float4*>(g_Xemb)[idx] =
            reinterpret_cast<const float4*>(emb)[(size_t)tok * (E_/4) + e4];
    }
}

__global__ void prep_k(const float* __restrict__ Wz, const float* __restrict__ Wr,
                       const float* __restrict__ Wn) {
    const int SS = S_ * S_;
    int idx = blockIdx.x * blockDim.x + threadIdx.x;
    const int stride = gridDim.x * blockDim.x;
    for (; idx < 6 * SS; idx += stride) {
        int k = idx & (S_ - 1);
        int c = (idx >> 10) & (S_ - 1);
        int t20 = idx >> 20;
        int j = t20 / 3, g = t20 - 3 * j;
        const float* W = (g == 0) ? Wz : (g == 1) ? Wr : Wn;
        g_WhT[idx] = W[((size_t)(j * (E_ + S_) + E_ + k)) * S_ + c];
    }
}

__global__ void convA_k(const float* __restrict__ src) {
    int i = blockIdx.x * blockDim.x + threadIdx.x;
    if (i < T_ * B_ * E_) {
        float x = src[i];
        __nv_bfloat16 h = __float2bfloat16(x);
        g_Ahi[i] = __bfloat16_as_ushort(h);
        g_Alo[i] = __bfloat16_as_ushort(__float2bfloat16(x - __bfloat162float(h)));
    }
}

__global__ void convW_k(const float* __restrict__ src, int ldn,
                        uint16_t* __restrict__ dhi, uint16_t* __restrict__ dlo, int K) {
    __shared__ float smt[32][33];
    int n0 = blockIdx.x * 32, k0 = blockIdx.y * 32;
    int tx = threadIdx.x, ty = threadIdx.y;
    smt[ty][tx] = src[(size_t)(k0 + ty) * ldn + n0 + tx];
    __syncthreads();
    float x = smt[tx][ty];
    __nv_bfloat16 h = __float2bfloat16(x);
    size_t o = (size_t)(n0 + ty) * K + k0 + tx;
    dhi[o] = __bfloat16_as_ushort(h);
    dlo[o] = __bfloat16_as_ushort(__float2bfloat16(x - __bfloat162float(h)));
}

// ------------------ mma.sync split-bf16 GEMM (unchanged, passing) -----------------
__device__ __forceinline__ uint32_t sw_addr(uint32_t base, int row, int chunk) {
    return base + row * 128 + (((chunk ^ (row & 7)) & 7) << 4);
}

__device__ __forceinline__ void load_chunk(
    uint32_t sb, const uint16_t* __restrict__ Ah, const uint16_t* __restrict__ Al,
    const uint16_t* __restrict__ Bh, const uint16_t* __restrict__ Bl,
    int m0, int n0, int c, int tid)
{
    const int ko = c * 64;
#pragma unroll
    for (int it = 0; it < 4; it++) {
        int o = tid + it * 256;
        int row = o >> 3, ch = o & 7;
        uint32_t dst = sw_addr(sb, row, ch);
        const size_t goffA = (size_t)(m0 + row) * 1024 + ko + ch * 8;
        const size_t goffB = (size_t)(n0 + row) * 1024 + ko + ch * 8;
        cpa16(dst,         Ah + goffA);
        cpa16(dst + 16384, Al + goffA);
        cpa16(dst + 32768, Bh + goffB);
        cpa16(dst + 49152, Bl + goffB);
    }
}

__global__ __launch_bounds__(256, 1) void tc_gemm(
    const uint16_t* __restrict__ Ah, const uint16_t* __restrict__ Al,
    const uint16_t* __restrict__ Bh, const uint16_t* __restrict__ Bl,
    const float* __restrict__ bias, float* __restrict__ C, int Ntot, int remap)
{
    extern __shared__ char smem[];
    const uint32_t sbase = smem_u32(smem);
    const int tid = threadIdx.x;
    const int w = tid >> 5, lane = tid & 31;
    const int m0 = blockIdx.x * 128;
    const int n0 = blockIdx.y * 128;
    const int wm = (w & 1) * 64, wn = (w >> 1) * 32;

    float acc[4][4][4];
#pragma unroll
    for (int i = 0; i < 4; i++)
#pragma unroll
        for (int j = 0; j < 4; j++)
#pragma unroll
            for (int q = 0; q < 4; q++) acc[i][j][q] = 0.f;

    const int sub = lane >> 3, l7 = lane & 7;
    const int a_row_off = (sub & 1) * 8 + l7;
    const int a_ch_off  = sub >> 1;
    const int b_row_off = (sub >> 1) * 8 + l7;
    const int b_ch_off  = sub & 1;

    load_chunk(sbase, Ah, Al, Bh, Bl, m0, n0, 0, tid);
    cpa_commit();

    for (int c = 0; c < NC_; c++) {
        if (c + 1 < NC_) {
            load_chunk(sbase + ((c + 1) & 1) * STAGE_BYTES, Ah, Al, Bh, Bl, m0, n0, c + 1, tid);
            cpa_commit();
            cpa_wait<1>();
        } else {
            cpa_wait<0>();
        }
        __syncthreads();

        const uint32_t sAh = sbase + (c & 1) * STAGE_BYTES;
        const uint32_t sAl = sAh + 16384;
        const uint32_t sBh = sAh + 32768;
        const uint32_t sBl = sAh + 49152;

#pragma unroll
        for (int kk = 0; kk < 4; kk++) {
            uint32_t Afh[4][4], Afl[4][4], Bfh[4][2], Bfl[4][2];
#pragma unroll
            for (int mt = 0; mt < 4; mt++) {
                int row = wm + mt * 16 + a_row_off;
                int ch = kk * 2 + a_ch_off;
                LDSM4(Afh[mt][0], Afh[mt][1], Afh[mt][2], Afh[mt][3], sw_addr(sAh, row, ch));
                LDSM4(Afl[mt][0], Afl[mt][1], Afl[mt][2], Afl[mt][3], sw_addr(sAl, row, ch));
            }
#pragma unroll
            for (int pr = 0; pr < 2; pr++) {
                int row = wn + pr * 16 + b_row_off;
                int ch = kk * 2 + b_ch_off;
                LDSM4(Bfh[2*pr][0], Bfh[2*pr][1], Bfh[2*pr+1][0], Bfh[2*pr+1][1],
                      sw_addr(sBh, row, ch));
                LDSM4(Bfl[2*pr][0], Bfl[2*pr][1], Bfl[2*pr+1][0], Bfl[2*pr+1][1],
                      sw_addr(sBl, row, ch));
            }
#pragma unroll
            for (int mt = 0; mt < 4; mt++)
#pragma unroll
                for (int nt = 0; nt < 4; nt++) {
                    MMA16816(acc[mt][nt], Afh[mt], Bfh[nt]);
                    MMA16816(acc[mt][nt], Afh[mt], Bfl[nt]);
                    MMA16816(acc[mt][nt], Afl[mt], Bfh[nt]);
                }
        }
        __syncthreads();
    }

    const int er = lane >> 2, ec = (lane & 3) * 2;
#pragma unroll
    for (int mt = 0; mt < 4; mt++) {
#pragma unroll
        for (int nt = 0; nt < 4; nt++) {
            int col = n0 + wn + nt * 8 + ec;
            float b0 = bias[col], b1 = bias[col + 1];
            int m1 = m0 + wm + mt * 16 + er;
            int m2 = m1 + 8;
            int r1 = remap ? ((m1 & 15) * T_ + (m1 >> 4)) : m1;
            int r2 = remap ? ((m2 & 15) * T_ + (m2 >> 4)) : m2;
            float2 v1 = make_float2(acc[mt][nt][0] + b0, acc[mt][nt][1] + b1);
            float2 v2 = make_float2(acc[mt][nt][2] + b0, acc[mt][nt][3] + b1);
            *reinterpret_cast<float2*>(C + (size_t)r1 * Ntot + col) = v1;
            *reinterpret_cast<float2*>(C + (size_t)r2 * Ntot + col) = v2;
        }
    }
}

// ------------------ persistent single-layer recurrence (f32x2, 256 thr) ----------
__device__ __forceinline__ void flag_barrier(unsigned int e) {
    __syncthreads();
    if (threadIdx.x == 0) {
        __threadfence();
        *((volatile unsigned int*)&g_flags[blockIdx.x]) = e;
    }
    if (threadIdx.x < 32) {
        const int lane = threadIdx.x;
        for (;;) {
            bool ok = true;
            for (int i = lane; i < (int)gridDim.x; i += 32)
                ok &= (*((volatile const unsigned int*)&g_flags[i]) >= e);
            if (__all_sync(0xffffffffu, ok)) break;
            __nanosleep(64);
        }
        __threadfence();
    }
    __syncthreads();
}

// async broadcast: gmem (L2-coherent) -> smem
__device__ __forceinline__ void load_sh(uint32_t dst, const float* __restrict__ src, int tid) {
#pragma unroll
    for (int i = tid; i < B_ * S_ / 4; i += RTHR) cpa16(dst + i * 16, src + i * 4);
    cpa_commit();
    cpa_wait<0>();
}

// stage A: 4 dots (c0:z,r  c1:z,r) over k-major h; acc entries [d*8+bp] pack (2bp,2bp+1)
__device__ __forceinline__ void dotA(const float* __restrict__ wz0, const float* __restrict__ wr0,
                                     const float* __restrict__ wz1, const float* __restrict__ wr1,
                                     const float* __restrict__ sh, int lane, u64 acc[32]) {
#pragma unroll
    for (int kk = 0; kk < 8; kk++) {
        const int k0 = kk * 128 + lane * 4;
        float4 a = *reinterpret_cast<const float4*>(wz0 + k0);
        float4 b = *reinterpret_cast<const float4*>(wr0 + k0);
        float4 c = *reinterpret_cast<const float4*>(wz1 + k0);
        float4 d = *reinterpret_cast<const float4*>(wr1 + k0);
        float wa[4] = {a.x, a.y, a.z, a.w};
        float wb[4] = {b.x, b.y, b.z, b.w};
        float wc[4] = {c.x, c.y, c.z, c.w};
        float wd[4] = {d.x, d.y, d.z, d.w};
#pragma unroll
        for (int q = 0; q < 4; q++) {
            const ulonglong2* hp = reinterpret_cast<const ulonglong2*>(sh + (size_t)(k0 + q) * 16);
            ulonglong2 h0 = hp[0], h1 = hp[1], h2 = hp[2], h3 = hp[3];
            u64 w0 = dup2(wa[q]), w1 = dup2(wb[q]), w2 = dup2(wc[q]), w3 = dup2(wd[q]);
            fma2(acc[0], w0, h0.x); fma2(acc[1], w0, h0.y);
            fma2(acc[2], w0, h1.x); fma2(acc[3], w0, h1.y);
            fma2(acc[4], w0, h2.x); fma2(acc[5], w0, h2.y);
            fma2(acc[6], w0, h3.x); fma2(acc[7], w0, h3.y);
            fma2(acc[8],  w1, h0.x); fma2(acc[9],  w1, h0.y);
            fma2(acc[10], w1, h1.x); fma2(acc[11], w1, h1.y);
            fma2(acc[12], w1, h2.x); fma2(acc[13], w1, h2.y);
            fma2(acc[14], w1, h3.x); fma2(acc[15], w1, h3.y);
            fma2(acc[16], w2, h0.x); fma2(acc[17], w2, h0.y);
            fma2(acc[18], w2, h1.x); fma2(acc[19], w2, h1.y);
            fma2(acc[20], w2, h2.x); fma2(acc[21], w2, h2.y);
            fma2(acc[22], w2, h3.x); fma2(acc[23], w2, h3.y);
            fma2(acc[24], w3, h0.x); fma2(acc[25], w3, h0.y);
            fma2(acc[26], w3, h1.x); fma2(acc[27], w3, h1.y);
            fma2(acc[28], w3, h2.x); fma2(acc[29], w3, h2.y);
            fma2(acc[30], w3, h3.x); fma2(acc[31], w3, h3.y);
        }
    }
}

// stage B: 2 dots (n at c0, c1)
__device__ __forceinline__ void dotB(const float* __restrict__ wn0, const float* __restrict__ wn1,
                                     const float* __restrict__ sh, int lane, u64 acc[16]) {
#pragma unroll
    for (int kk = 0; kk < 8; kk++) {
        const int k0 = kk * 128 + lane * 4;
        float4 a = *reinterpret_cast<const float4*>(wn0 + k0);
        float4 b = *reinterpret_cast<const float4*>(wn1 + k0);
        float wa[4] = {a.x, a.y, a.z, a.w};
        float wb[4] = {b.x, b.y, b.z, b.w};
#pragma unroll
        for (int q = 0; q < 4; q++) {
            const ulonglong2* hp = reinterpret_cast<const ulonglong2*>(sh + (size_t)(k0 + q) * 16);
            ulonglong2 h0 = hp[0], h1 = hp[1], h2 = hp[2], h3 = hp[3];
            u64 w0 = dup2(wa[q]), w1 = dup2(wb[q]);
            fma2(acc[0], w0, h0.x); fma2(acc[1], w0, h0.y);
            fma2(acc[2], w0, h1.x); fma2(acc[3], w0, h1.y);
            fma2(acc[4], w0, h2.x); fma2(acc[5], w0, h2.y);
            fma2(acc[6], w0, h3.x); fma2(acc[7], w0, h3.y);
            fma2(acc[8],  w1, h0.x); fma2(acc[9],  w1, h0.y);
            fma2(acc[10], w1, h1.x); fma2(acc[11], w1, h1.y);
            fma2(acc[12], w1, h2.x); fma2(acc[13], w1, h2.y);
            fma2(acc[14], w1, h3.x); fma2(acc[15], w1, h3.y);
        }
    }
}

// butterfly-fold 32 packed entries across 32 lanes; lane l ends with entry l
__device__ __forceinline__ u64 reduce32p(u64 acc[32], int lane) {
    int cnt = 32;
#pragma unroll
    for (int off = 16; off >= 1; off >>= 1) {
        const bool up = (lane & off) != 0;
        const int half = cnt >> 1;
#pragma unroll
        for (int i = 0; i < 16; i++) {
            if (i < half) {
                u64 send = up ? acc[i] : acc[i + half];
                u64 recv = shfl64(send, off);
                acc[i] = add2(up ? acc[i + half] : acc[i], recv);
            }
        }
        cnt = half;
    }
    return acc[0];
}

// 16 entries: plain add at off=16, then fold; lane l ends with entry (l & 15)
__device__ __forceinline__ u64 reduce16p(u64 acc[16], int lane) {
#pragma unroll
    for (int i = 0; i < 16; i++) acc[i] = add2(acc[i], shfl64(acc[i], 16));
    int cnt = 16;
#pragma unroll
    for (int off = 8; off >= 1; off >>= 1) {
        const bool up = (lane & off) != 0;
        const int half = cnt >> 1;
#pragma unroll
        for (int i = 0; i < 8; i++) {
            if (i < half) {
                u64 send = up ? acc[i] : acc[i + half];
                u64 recv = shfl64(send, off);
                acc[i] = add2(up ? acc[i + half] : acc[i], recv);
            }
        }
        cnt = half;
    }
    return acc[0];
}

__global__ __launch_bounds__(RTHR, 1) void gru_pass(
    const float* __restrict__ Xz, const float* __restrict__ Xr,
    const float* __restrict__ Xn, const float* __restrict__ WhT,
    float* __restrict__ hbuf, float* __restrict__ Hseq, unsigned int ebase)
{
    extern __shared__ float sh[];
    float* shA = sh;              // h  [k*16+b]
    float* shB = sh + B_ * S_;    // rh [k*16+b]
    const uint32_t shAa = smem_u32(shA), shBa = smem_u32(shB);
    const int tid = threadIdx.x, lane = tid & 31, wib = tid >> 5, bid = blockIdx.x;
    const int p = wib * NBLK + bid;          // warp work unit (8 warps/block)
    const bool act = (p < S_ / 2);
    const int c0 = 2 * p, c1 = 2 * p + 1;

    const int dA = lane >> 3, bpA = lane & 7;
    const int colA = c0 + (dA >> 1);
    const int gateA = dA & 1;
    const int bA0 = 2 * bpA;
    const int dB = (lane & 15) >> 3, bpB = lane & 7;
    const int colB = c0 + dB;
    const int bB0 = 2 * bpB;

    const float* wz0 = WhT + ((size_t)0 * S_ + c0) * S_;
    const float* wr0 = WhT + ((size_t)1 * S_ + c0) * S_;
    const float* wz1 = WhT + ((size_t)0 * S_ + c1) * S_;
    const float* wr1 = WhT + ((size_t)1 * S_ + c1) * S_;
    const float* wn0 = WhT + ((size_t)2 * S_ + c0) * S_;
    const float* wn1 = WhT + ((size_t)2 * S_ + c1) * S_;

    for (int i = tid; i < B_ * S_; i += RTHR) shA[i] = 0.f;
    __syncthreads();

    for (int t = 0; t < T_; t++) {
        // ---- stage A: z, r ----
        if (act) {
            const float* Xg = gateA ? Xr : Xz;
            float px0 = __ldcg(&Xg[((size_t)t * B_ + bA0) * S_ + colA]);
            float px1 = __ldcg(&Xg[((size_t)t * B_ + bA0 + 1) * S_ + colA]);
            u64 acc[32];
#pragma unroll
            for (int i = 0; i < 32; i++) acc[i] = 0ull;
            dotA(wz0, wr0, wz1, wr1, shA, lane, acc);
            float2 sv = unpack2(reduce32p(acc, lane));
            float g0 = 1.f / (1.f + __expf(-(px0 + sv.x)));
            float g1 = 1.f / (1.f + __expf(-(px1 + sv.y)));
            if (gateA == 0) {
                __stcg((float2*)&g_zbuf[colA * 16 + bA0], make_float2(g0, g1));
            } else {
                float2 h2 = *(const float2*)&shA[colA * 16 + bA0];
                __stcg((float2*)&g_rhbuf[colA * 16 + bA0], make_float2(g0 * h2.x, g1 * h2.y));
            }
        }
        flag_barrier(ebase + 2 * t + 1);
        load_sh(shBa, g_rhbuf, tid);
        __syncthreads();

        // ---- stage B: n + h update ----
        if (act) {
            float pn0 = __ldcg(&Xn[((size_t)t * B_ + bB0) * S_ + colB]);
            float pn1 = __ldcg(&Xn[((size_t)t * B_ + bB0 + 1) * S_ + colB]);
            u64 acc[16];
#pragma unroll
            for (int i = 0; i < 16; i++) acc[i] = 0ull;
            dotB(wn0, wn1, shB, lane, acc);
            float2 sv = unpack2(reduce16p(acc, lane));
            float n0 = tanhf(pn0 + sv.x);
            float n1 = tanhf(pn1 + sv.y);
            float2 z2 = __ldcg((const float2*)&g_zbuf[colB * 16 + bB0]);
            float2 ho = *(const float2*)&shA[colB * 16 + bB0];
            float hn0 = ho.x + z2.x * (n0 - ho.x);
            float hn1 = ho.y + z2.y * (n1 - ho.y);
            __stcg((float2*)&hbuf[colB * 16 + bB0], make_float2(hn0, hn1));
            __stcg(&Hseq[((size_t)t * B_ + bB0) * S_ + colB], hn0);
            __stcg(&Hseq[((size_t)t * B_ + bB0 + 1) * S_ + colB], hn1);
        }
        flag_barrier(ebase + 2 * t + 2);
        load_sh(shAa, hbuf, tid);
        __syncthreads();
    }
}

__global__ void copy_h_k(float* __restrict__ hout) {
    int i = blockIdx.x * blockDim.x + threadIdx.x;
    if (i < B_ * S_) {
        int b = i >> 10, c = i & (S_ - 1);
        hout[i]           = g_hb0[c * 16 + b];
        hout[B_ * S_ + i] = g_hb1[c * 16 + b];
    }
}

// ------------------ launch --------------------------------------------------------
extern "C" void kernel_launch(void* const* d_in, const int* in_sizes, int n_in,
                              void* d_out, int out_size) {
    const int*   x   = (const int*)  d_in[0];
    const float* emb = (const float*)d_in[1];
    const float* Wz  = (const float*)d_in[2];
    const float* bz  = (const float*)d_in[3];
    const float* Wr  = (const float*)d_in[4];
    const float* br  = (const float*)d_in[5];
    const float* Wn  = (const float*)d_in[6];
    const float* bn  = (const float*)d_in[7];
    const float* Wo  = (const float*)d_in[8];
    const float* bo  = (const float*)d_in[9];
    float* out = (float*)d_out;
    (void)in_sizes; (void)n_in;

    const int smem_rec = 2 * B_ * S_ * (int)sizeof(float);     // 128 KB
    const int smem_tc  = 2 * STAGE_BYTES;                       // 128 KB
    cudaFuncSetAttribute(gru_pass, cudaFuncAttributeMaxDynamicSharedMemorySize, smem_rec);
    cudaFuncSetAttribute(tc_gemm,  cudaFuncAttributeMaxDynamicSharedMemorySize, smem_tc);

    float *Xemb, *Xz0, *Xr0, *Xn0, *H2, *WhT, *hb0, *hb1;
    uint16_t *Ahi, *Alo, *Whi, *Wlo;
    cudaGetSymbolAddress((void**)&Xemb, g_Xemb);
    cudaGetSymbolAddress((void**)&Xz0, g_Xz0);
    cudaGetSymbolAddress((void**)&Xr0, g_Xr0);
    cudaGetSymbolAddress((void**)&Xn0, g_Xn0);
    cudaGetSymbolAddress((void**)&H2,  g_H2);
    cudaGetSymbolAddress((void**)&WhT, g_WhT);
    cudaGetSymbolAddress((void**)&hb0, g_hb0);
    cudaGetSymbolAddress((void**)&hb1, g_hb1);
    cudaGetSymbolAddress((void**)&Ahi, g_Ahi);
    cudaGetSymbolAddress((void**)&Alo, g_Alo);
    cudaGetSymbolAddress((void**)&Whi, g_Whi);
    cudaGetSymbolAddress((void**)&Wlo, g_Wlo);

    float* hout = nullptr;
    long long need = (long long)B_ * T_ * V_ + 2LL * B_ * S_;
    if ((long long)out_size >= need) hout = out + (size_t)B_ * T_ * V_;

    const size_t SS = (size_t)S_ * S_;

    reset_k<<<1, 256>>>();
    prep_k<<<4608, 256>>>(Wz, Wr, Wn);
    embed_k<<<1024, 256>>>(x, emb);

    dim3 cb(32, 32);
    dim3 cgGate(S_ / 32, S_ / 32);
    convW_k<<<cgGate, cb>>>(Wz,                          S_, Whi + 0 * SS, Wlo + 0 * SS, S_);
    convW_k<<<cgGate, cb>>>(Wr,                          S_, Whi + 1 * SS, Wlo + 1 * SS, S_);
    convW_k<<<cgGate, cb>>>(Wn,                          S_, Whi + 2 * SS, Wlo + 2 * SS, S_);
    convW_k<<<cgGate, cb>>>(Wz + (size_t)(E_ + S_) * S_, S_, Whi + 3 * SS, Wlo + 3 * SS, S_);
    convW_k<<<cgGate, cb>>>(Wr + (size_t)(E_ + S_) * S_, S_, Whi + 4 * SS, Wlo + 4 * SS, S_);
    convW_k<<<cgGate, cb>>>(Wn + (size_t)(E_ + S_) * S_, S_, Whi + 5 * SS, Wlo + 5 * SS, S_);
    dim3 cgVoc(V_ / 32, S_ / 32);
    convW_k<<<cgVoc, cb>>>(Wo, V_, Whi + 6 * SS, Wlo + 6 * SS, S_);

    const int nA = T_ * B_ * E_;
    dim3 gproj((T_ * B_) / 128, S_ / 128);

    convA_k<<<(nA + 255) / 256, 256>>>(Xemb);
    tc_gemm<<<gproj, 256, smem_tc>>>(Ahi, Alo, Whi + 0 * SS, Wlo + 0 * SS, bz, Xz0, S_, 0);
    tc_gemm<<<gproj, 256, smem_tc>>>(Ahi, Alo, Whi + 1 * SS, Wlo + 1 * SS, br, Xr0, S_, 0);
    tc_gemm<<<gproj, 256, smem_tc>>>(Ahi, Alo, Whi + 2 * SS, Wlo + 2 * SS, bn, Xn0, S_, 0);

    gru_pass<<<NBLK, RTHR, smem_rec>>>(Xz0, Xr0, Xn0, WhT, hb0, Xemb, 0u);

    convA_k<<<(nA + 255) / 256, 256>>>(Xemb);
    tc_gemm<<<gproj, 256, smem_tc>>>(Ahi, Alo, Whi + 3 * SS, Wlo + 3 * SS, bz + S_, Xz0, S_, 0);
    tc_gemm<<<gproj, 256, smem_tc>>>(Ahi, Alo, Whi + 4 * SS, Wlo + 4 * SS, br + S_, Xr0, S_, 0);
    tc_gemm<<<gproj, 256, smem_tc>>>(Ahi, Alo, Whi + 5 * SS, Wlo + 5 * SS, bn + S_, Xn0, S_, 0);

    gru_pass<<<NBLK, RTHR, smem_rec>>>(Xz0, Xr0, Xn0, WhT + 3 * SS, hb1, H2, 2u * T_);

    convA_k<<<(nA + 255) / 256, 256>>>(H2);
    dim3 gout((T_ * B_) / 128, V_ / 128);
    tc_gemm<<<gout, 256, smem_tc>>>(Ahi, Alo, Whi + 6 * SS, Wlo + 6 * SS, bo, out, V_, 1);

    if (hout) copy_h_k<<<(B_ * S_ + 255) / 256, 256>>>(hout);
}

// round 12
// speedup vs baseline: 1.7080x; 1.7080x over previous
#include <cuda_runtime.h>
#include <cuda_bf16.h>
#include <math.h>
#include <stdint.h>

#define B_ 16
#define T_ 256
#define S_ 1024
#define E_ 1024
#define V_ 32000
#define NBLK 148
#define RT_ 384                       // recurrence block size (reg cap ~168 > ~110 needed)
#define NC_ 16                        // K chunks of 64 (GEMM)
#define STAGE_BYTES 65536             // Ahi/Alo/Bhi/Blo, 16 KB each

typedef unsigned long long u64;

// ------------------ scratch (device globals; no allocation allowed) -------------
__device__ float g_Xemb[T_*B_*E_];      // embeddings; later reused as H1
__device__ float g_Xz0[T_*B_*S_];
__device__ float g_Xr0[T_*B_*S_];
__device__ float g_Xn0[T_*B_*S_];
__device__ float g_H2[T_*B_*S_];
__device__ float g_WhT[6*S_*S_];        // fp32 transposed hidden weights (recurrence)
__device__ float g_hb0[B_*S_];          // [b*S + c]
__device__ float g_hb1[B_*S_];
__device__ float g_zbuf[B_*S_];
__device__ float g_rhbuf[B_*S_];
__device__ unsigned int g_flags[256];
// bf16 split operands for tensor-core GEMMs
__device__ uint16_t g_Ahi[T_*B_*E_];
__device__ uint16_t g_Alo[T_*B_*E_];
__device__ uint16_t g_Whi[6*S_*S_ + V_*S_];
__device__ uint16_t g_Wlo[6*S_*S_ + V_*S_];

// ------------------ PTX helpers --------------------------------------------------
__device__ __forceinline__ uint32_t smem_u32(const void* p) {
    uint32_t a;
    asm("{ .reg .u64 t; cvta.to.shared.u64 t, %1; cvt.u32.u64 %0, t; }" : "=r"(a) : "l"(p));
    return a;
}
__device__ __forceinline__ void cpa16(uint32_t s, const void* g) {
    asm volatile("cp.async.cg.shared.global [%0], [%1], 16;" :: "r"(s), "l"(g));
}
__device__ __forceinline__ void cpa_commit() { asm volatile("cp.async.commit_group;"); }
template <int N> __device__ __forceinline__ void cpa_wait() {
    asm volatile("cp.async.wait_group %0;" :: "n"(N));
}
#define LDSM4(r0, r1, r2, r3, a) \
    asm volatile("ldmatrix.sync.aligned.m8n8.x4.shared.b16 {%0,%1,%2,%3}, [%4];" \
        : "=r"(r0), "=r"(r1), "=r"(r2), "=r"(r3) : "r"(a))
#define MMA16816(d, a, b) \
    asm volatile("mma.sync.aligned.m16n8k16.row.col.f32.bf16.bf16.f32 " \
        "{%0,%1,%2,%3}, {%4,%5,%6,%7}, {%8,%9}, {%0,%1,%2,%3};" \
        : "+f"((d)[0]), "+f"((d)[1]), "+f"((d)[2]), "+f"((d)[3]) \
        : "r"((a)[0]), "r"((a)[1]), "r"((a)[2]), "r"((a)[3]), "r"((b)[0]), "r"((b)[1]))

// packed f32x2 ops (baseline sm_100+, PTX-only)
__device__ __forceinline__ void fma2(u64& d, u64 a, u64 b) {
    asm("fma.rn.f32x2 %0, %1, %2, %0;" : "+l"(d) : "l"(a), "l"(b));
}
__device__ __forceinline__ u64 add2(u64 a, u64 b) {
    u64 r; asm("add.rn.f32x2 %0, %1, %2;" : "=l"(r) : "l"(a), "l"(b)); return r;
}
__device__ __forceinline__ u64 pack2(float x, float y) {
    u64 r; asm("mov.b64 %0, {%1, %2};" : "=l"(r) : "f"(x), "f"(y)); return r;
}
__device__ __forceinline__ float2 unpack2(u64 v) {
    float2 r; asm("mov.b64 {%0, %1}, %2;" : "=f"(r.x), "=f"(r.y) : "l"(v)); return r;
}
__device__ __forceinline__ u64 shfl64(u64 v, int off) {
    return __shfl_xor_sync(0xffffffffu, v, off);
}

// ------------------ small utility kernels ---------------------------------------
__global__ void reset_k() { if (threadIdx.x < 256) g_flags[threadIdx.x] = 0u; }

__global__ void embed_k(const int* __restrict__ x, const float* __restrict__ emb) {
    int idx = blockIdx.x * blockDim.x + threadIdx.x;
    const int total = T_ * B_ * (E_ / 4);
    const int stride = gridDim.x * blockDim.x;
    for (; idx < total; idx += stride) {
        int e4 = idx & (E_/4 - 1);
        int tb = idx >> 8;
        int t = tb >> 4, b = tb & 15;
        int tok = x[b * T_ + t];
        reinterpret_cast<float4*>(g_Xemb)[idx] =
            reinterpret_cast<const float4*>(emb)[(size_t)tok * (E_/4) + e4];
    }
}

__global__ void prep_k(const float* __restrict__ Wz, const float* __restrict__ Wr,
                       const float* __restrict__ Wn) {
    const int SS = S_ * S_;
    int idx = blockIdx.x * blockDim.x + threadIdx.x;
    const int stride = gridDim.x * blockDim.x;
    for (; idx < 6 * SS; idx += stride) {
        int k = idx & (S_ - 1);
        int c = (idx >> 10) & (S_ - 1);
        int t20 = idx >> 20;
        int j = t20 / 3, g = t20 - 3 * j;
        const float* W = (g == 0) ? Wz : (g == 1) ? Wr : Wn;
        g_WhT[idx] = W[((size_t)(j * (E_ + S_) + E_ + k)) * S_ + c];
    }
}

__global__ void convA_k(const float* __restrict__ src) {
    int i = blockIdx.x * blockDim.x + threadIdx.x;
    if (i < T_ * B_ * E_) {
        float x = src[i];
        __nv_bfloat16 h = __float2bfloat16(x);
        g_Ahi[i] = __bfloat16_as_ushort(h);
        g_Alo[i] = __bfloat16_as_ushort(__float2bfloat16(x - __bfloat162float(h)));
    }
}

__global__ void convW_k(const float* __restrict__ src, int ldn,
                        uint16_t* __restrict__ dhi, uint16_t* __restrict__ dlo, int K) {
    __shared__ float smt[32][33];
    int n0 = blockIdx.x * 32, k0 = blockIdx.y * 32;
    int tx = threadIdx.x, ty = threadIdx.y;
    smt[ty][tx] = src[(size_t)(k0 + ty) * ldn + n0 + tx];
    __syncthreads();
    float x = smt[tx][ty];
    __nv_bfloat16 h = __float2bfloat16(x);
    size_t o = (size_t)(n0 + ty) * K + k0 + tx;
    dhi[o] = __bfloat16_as_ushort(h);
    dlo[o] = __bfloat16_as_ushort(__float2bfloat16(x - __bfloat162float(h)));
}

// ------------------ mma.sync split-bf16 GEMM (unchanged, passing) -----------------
__device__ __forceinline__ uint32_t sw_addr(uint32_t base, int row, int chunk) {
    return base + row * 128 + (((chunk ^ (row & 7)) & 7) << 4);
}

__device__ __forceinline__ void load_chunk(
    uint32_t sb, const uint16_t* __restrict__ Ah, const uint16_t* __restrict__ Al,
    const uint16_t* __restrict__ Bh, const uint16_t* __restrict__ Bl,
    int m0, int n0, int c, int tid)
{
    const int ko = c * 64;
#pragma unroll
    for (int it = 0; it < 4; it++) {
        int o = tid + it * 256;
        int row = o >> 3, ch = o & 7;
        uint32_t dst = sw_addr(sb, row, ch);
        const size_t goffA = (size_t)(m0 + row) * 1024 + ko + ch * 8;
        const size_t goffB = (size_t)(n0 + row) * 1024 + ko + ch * 8;
        cpa16(dst,         Ah + goffA);
        cpa16(dst + 16384, Al + goffA);
        cpa16(dst + 32768, Bh + goffB);
        cpa16(dst + 49152, Bl + goffB);
    }
}

__global__ __launch_bounds__(256, 1) void tc_gemm(
    const uint16_t* __restrict__ Ah, const uint16_t* __restrict__ Al,
    const uint16_t* __restrict__ Bh, const uint16_t* __restrict__ Bl,
    const float* __restrict__ bias, float* __restrict__ C, int Ntot, int remap)
{
    extern __shared__ char smem[];
    const uint32_t sbase = smem_u32(smem);
    const int tid = threadIdx.x;
    const int w = tid >> 5, lane = tid & 31;
    const int m0 = blockIdx.x * 128;
    const int n0 = blockIdx.y * 128;
    const int wm = (w & 1) * 64, wn = (w >> 1) * 32;

    float acc[4][4][4];
#pragma unroll
    for (int i = 0; i < 4; i++)
#pragma unroll
        for (int j = 0; j < 4; j++)
#pragma unroll
            for (int q = 0; q < 4; q++) acc[i][j][q] = 0.f;

    const int sub = lane >> 3, l7 = lane & 7;
    const int a_row_off = (sub & 1) * 8 + l7;
    const int a_ch_off  = sub >> 1;
    const int b_row_off = (sub >> 1) * 8 + l7;
    const int b_ch_off  = sub & 1;

    load_chunk(sbase, Ah, Al, Bh, Bl, m0, n0, 0, tid);
    cpa_commit();

    for (int c = 0; c < NC_; c++) {
        if (c + 1 < NC_) {
            load_chunk(sbase + ((c + 1) & 1) * STAGE_BYTES, Ah, Al, Bh, Bl, m0, n0, c + 1, tid);
            cpa_commit();
            cpa_wait<1>();
        } else {
            cpa_wait<0>();
        }
        __syncthreads();

        const uint32_t sAh = sbase + (c & 1) * STAGE_BYTES;
        const uint32_t sAl = sAh + 16384;
        const uint32_t sBh = sAh + 32768;
        const uint32_t sBl = sAh + 49152;

#pragma unroll
        for (int kk = 0; kk < 4; kk++) {
            uint32_t Afh[4][4], Afl[4][4], Bfh[4][2], Bfl[4][2];
#pragma unroll
            for (int mt = 0; mt < 4; mt++) {
                int row = wm + mt * 16 + a_row_off;
                int ch = kk * 2 + a_ch_off;
                LDSM4(Afh[mt][0], Afh[mt][1], Afh[mt][2], Afh[mt][3], sw_addr(sAh, row, ch));
                LDSM4(Afl[mt][0], Afl[mt][1], Afl[mt][2], Afl[mt][3], sw_addr(sAl, row, ch));
            }
#pragma unroll
            for (int pr = 0; pr < 2; pr++) {
                int row = wn + pr * 16 + b_row_off;
                int ch = kk * 2 + b_ch_off;
                LDSM4(Bfh[2*pr][0], Bfh[2*pr][1], Bfh[2*pr+1][0], Bfh[2*pr+1][1],
                      sw_addr(sBh, row, ch));
                LDSM4(Bfl[2*pr][0], Bfl[2*pr][1], Bfl[2*pr+1][0], Bfl[2*pr+1][1],
                      sw_addr(sBl, row, ch));
            }
#pragma unroll
            for (int mt = 0; mt < 4; mt++)
#pragma unroll
                for (int nt = 0; nt < 4; nt++) {
                    MMA16816(acc[mt][nt], Afh[mt], Bfh[nt]);
                    MMA16816(acc[mt][nt], Afh[mt], Bfl[nt]);
                    MMA16816(acc[mt][nt], Afl[mt], Bfh[nt]);
                }
        }
        __syncthreads();
    }

    const int er = lane >> 2, ec = (lane & 3) * 2;
#pragma unroll
    for (int mt = 0; mt < 4; mt++) {
#pragma unroll
        for (int nt = 0; nt < 4; nt++) {
            int col = n0 + wn + nt * 8 + ec;
            float b0 = bias[col], b1 = bias[col + 1];
            int m1 = m0 + wm + mt * 16 + er;
            int m2 = m1 + 8;
            int r1 = remap ? ((m1 & 15) * T_ + (m1 >> 4)) : m1;
            int r2 = remap ? ((m2 & 15) * T_ + (m2 >> 4)) : m2;
            float2 v1 = make_float2(acc[mt][nt][0] + b0, acc[mt][nt][1] + b1);
            float2 v2 = make_float2(acc[mt][nt][2] + b0, acc[mt][nt][3] + b1);
            *reinterpret_cast<float2*>(C + (size_t)r1 * Ntot + col) = v1;
            *reinterpret_cast<float2*>(C + (size_t)r2 * Ntot + col) = v2;
        }
    }
}

// ------------------ persistent single-layer recurrence ---------------------------
// R8-proven layout (h b-major in smem, conflict-free float4 lane access) with the
// inner FMAs packed along k via fma.rn.f32x2 (half the FFMA issue count).
__device__ __forceinline__ void flag_barrier(unsigned int e) {
    __syncthreads();
    if (threadIdx.x == 0) {
        __threadfence();
        *((volatile unsigned int*)&g_flags[blockIdx.x]) = e;
    }
    if (threadIdx.x < 32) {
        const int lane = threadIdx.x;
        for (;;) {
            bool ok = true;
            for (int i = lane; i < (int)gridDim.x; i += 32)
                ok &= (*((volatile const unsigned int*)&g_flags[i]) >= e);
            if (__all_sync(0xffffffffu, ok)) break;
            __nanosleep(200);
        }
        __threadfence();
    }
    __syncthreads();
}

__device__ __forceinline__ void load_sh(float* dst, const float* src, int tid) {
    const float4* s4 = reinterpret_cast<const float4*>(src);
    float4* d4 = reinterpret_cast<float4*>(dst);
#pragma unroll
    for (int i = tid; i < B_ * S_ / 4; i += RT_) d4[i] = __ldcg(s4 + i);
}

// Dual dot over b-major smem h: acc[0..15] vs w0, acc[16..31] vs w1, 16 batches.
// Each u64 acc holds (even-k partial, odd-k partial); caller sums .x+.y at the end.
__device__ __forceinline__ void dual_dot2(const float* __restrict__ w0row,
                                          const float* __restrict__ w1row,
                                          const float* __restrict__ sh,
                                          int lane, u64 acc[32]) {
    const float4* w04 = reinterpret_cast<const float4*>(w0row);
    const float4* w14 = reinterpret_cast<const float4*>(w1row);
#pragma unroll
    for (int kk = 0; kk < 8; kk++) {
        float4 a = w04[kk * 32 + lane];
        float4 b = w14[kk * 32 + lane];
        u64 a_lo = pack2(a.x, a.y), a_hi = pack2(a.z, a.w);
        u64 b_lo = pack2(b.x, b.y), b_hi = pack2(b.z, b.w);
        int kb = (kk * 32 + lane) * 4;
#pragma unroll
        for (int bb = 0; bb < 16; bb++) {
            ulonglong2 h2 = *reinterpret_cast<const ulonglong2*>(sh + bb * S_ + kb);
            fma2(acc[bb],      a_lo, h2.x);
            fma2(acc[bb],      a_hi, h2.y);
            fma2(acc[16 + bb], b_lo, h2.x);
            fma2(acc[16 + bb], b_hi, h2.y);
        }
    }
}

// Folding butterfly over 32 packed entries; lane l ends with entry l (pairs intact).
__device__ __forceinline__ u64 reduce32p(u64 acc[32], int lane) {
    int cnt = 32;
#pragma unroll
    for (int off = 16; off >= 1; off >>= 1) {
        const bool up = (lane & off) != 0;
        const int half = cnt >> 1;
#pragma unroll
        for (int i = 0; i < 16; i++) {
            if (i < half) {
                u64 send = up ? acc[i] : acc[i + half];
                u64 recv = shfl64(send, off);
                acc[i] = add2(up ? acc[i + half] : acc[i], recv);
            }
        }
        cnt = half;
    }
    return acc[0];
}

__global__ __launch_bounds__(RT_, 1) void gru_pass(
    const float* __restrict__ Xz, const float* __restrict__ Xr,
    const float* __restrict__ Xn, const float* __restrict__ WhT,
    float* __restrict__ hbuf, float* __restrict__ Hseq, unsigned int ebase)
{
    extern __shared__ float sh[];
    float* shA = sh;              // h   [b*S + k]
    float* shB = sh + B_ * S_;    // r*h [b*S + k]
    const int tid = threadIdx.x;
    const int lane = tid & 31;
    const int wib = tid >> 5;
    const int bid = blockIdx.x;
    const int pA = wib * NBLK + bid;

    for (int i = tid; i < B_ * S_; i += RT_) shA[i] = 0.f;
    __syncthreads();

    for (int t = 0; t < T_; ++t) {
        // ---- stage A: z and r at column pA ----
        if (pA < S_) {
            const float* w0 = WhT + ((size_t)0 * S_ + pA) * S_;   // Whz row
            const float* w1 = WhT + ((size_t)1 * S_ + pA) * S_;   // Whr row
            u64 acc[32];
#pragma unroll
            for (int i = 0; i < 32; i++) acc[i] = 0ull;
            dual_dot2(w0, w1, shA, lane, acc);
            float2 sv = unpack2(reduce32p(acc, lane));
            float s = sv.x + sv.y;
            int b = lane & 15;
            const float* Xg = (lane < 16) ? Xz : Xr;
            float pre = Xg[((size_t)t * B_ + b) * S_ + pA] + s;
            float sg = 1.f / (1.f + __expf(-pre));
            if (lane < 16) __stcg(&g_zbuf[b * S_ + pA], sg);
            else           __stcg(&g_rhbuf[b * S_ + pA], sg * shA[b * S_ + pA]);
        }
        flag_barrier(ebase + 2 * t + 1);
        load_sh(shB, g_rhbuf, tid);
        __syncthreads();

        // ---- stage B: n at columns 2pA, 2pA+1; h update ----
        if (pA < S_ / 2) {
            const int c0 = 2 * pA;
            const float* w0 = WhT + ((size_t)2 * S_ + c0) * S_;       // Whn rows
            const float* w1 = WhT + ((size_t)2 * S_ + c0 + 1) * S_;
            u64 acc[32];
#pragma unroll
            for (int i = 0; i < 32; i++) acc[i] = 0ull;
            dual_dot2(w0, w1, shB, lane, acc);
            float2 sv = unpack2(reduce32p(acc, lane));
            float s = sv.x + sv.y;
            int b = lane & 15;
            int col = c0 + (lane >> 4);
            float pre = Xn[((size_t)t * B_ + b) * S_ + col] + s;
            float n = tanhf(pre);
            float ho = shA[b * S_ + col];
            float z  = __ldcg(&g_zbuf[b * S_ + col]);
            float hn = ho + z * (n - ho);
            __stcg(&hbuf[b * S_ + col], hn);
            __stcg(&Hseq[((size_t)t * B_ + b) * S_ + col], hn);
        }
        flag_barrier(ebase + 2 * t + 2);
        load_sh(shA, hbuf, tid);
        __syncthreads();
    }
}

__global__ void copy_h_k(float* __restrict__ hout) {
    int i = blockIdx.x * blockDim.x + threadIdx.x;
    if (i < B_ * S_) {
        hout[i]           = g_hb0[i];
        hout[B_ * S_ + i] = g_hb1[i];
    }
}

// ------------------ launch --------------------------------------------------------
extern "C" void kernel_launch(void* const* d_in, const int* in_sizes, int n_in,
                              void* d_out, int out_size) {
    const int*   x   = (const int*)  d_in[0];
    const float* emb = (const float*)d_in[1];
    const float* Wz  = (const float*)d_in[2];
    const float* bz  = (const float*)d_in[3];
    const float* Wr  = (const float*)d_in[4];
    const float* br  = (const float*)d_in[5];
    const float* Wn  = (const float*)d_in[6];
    const float* bn  = (const float*)d_in[7];
    const float* Wo  = (const float*)d_in[8];
    const float* bo  = (const float*)d_in[9];
    float* out = (float*)d_out;
    (void)in_sizes; (void)n_in;

    const int smem_rec = 2 * B_ * S_ * (int)sizeof(float);     // 128 KB
    const int smem_tc  = 2 * STAGE_BYTES;                       // 128 KB
    cudaFuncSetAttribute(gru_pass, cudaFuncAttributeMaxDynamicSharedMemorySize, smem_rec);
    cudaFuncSetAttribute(tc_gemm,  cudaFuncAttributeMaxDynamicSharedMemorySize, smem_tc);

    float *Xemb, *Xz0, *Xr0, *Xn0, *H2, *WhT, *hb0, *hb1;
    uint16_t *Ahi, *Alo, *Whi, *Wlo;
    cudaGetSymbolAddress((void**)&Xemb, g_Xemb);
    cudaGetSymbolAddress((void**)&Xz0, g_Xz0);
    cudaGetSymbolAddress((void**)&Xr0, g_Xr0);
    cudaGetSymbolAddress((void**)&Xn0, g_Xn0);
    cudaGetSymbolAddress((void**)&H2,  g_H2);
    cudaGetSymbolAddress((void**)&WhT, g_WhT);
    cudaGetSymbolAddress((void**)&hb0, g_hb0);
    cudaGetSymbolAddress((void**)&hb1, g_hb1);
    cudaGetSymbolAddress((void**)&Ahi, g_Ahi);
    cudaGetSymbolAddress((void**)&Alo, g_Alo);
    cudaGetSymbolAddress((void**)&Whi, g_Whi);
    cudaGetSymbolAddress((void**)&Wlo, g_Wlo);

    float* hout = nullptr;
    long long need = (long long)B_ * T_ * V_ + 2LL * B_ * S_;
    if ((long long)out_size >= need) hout = out + (size_t)B_ * T_ * V_;

    const size_t SS = (size_t)S_ * S_;

    reset_k<<<1, 256>>>();
    prep_k<<<4608, 256>>>(Wz, Wr, Wn);
    embed_k<<<1024, 256>>>(x, emb);

    dim3 cb(32, 32);
    dim3 cgGate(S_ / 32, S_ / 32);
    convW_k<<<cgGate, cb>>>(Wz,                          S_, Whi + 0 * SS, Wlo + 0 * SS, S_);
    convW_k<<<cgGate, cb>>>(Wr,                          S_, Whi + 1 * SS, Wlo + 1 * SS, S_);
    convW_k<<<cgGate, cb>>>(Wn,                          S_, Whi + 2 * SS, Wlo + 2 * SS, S_);
    convW_k<<<cgGate, cb>>>(Wz + (size_t)(E_ + S_) * S_, S_, Whi + 3 * SS, Wlo + 3 * SS, S_);
    convW_k<<<cgGate, cb>>>(Wr + (size_t)(E_ + S_) * S_, S_, Whi + 4 * SS, Wlo + 4 * SS, S_);
    convW_k<<<cgGate, cb>>>(Wn + (size_t)(E_ + S_) * S_, S_, Whi + 5 * SS, Wlo + 5 * SS, S_);
    dim3 cgVoc(V_ / 32, S_ / 32);
    convW_k<<<cgVoc, cb>>>(Wo, V_, Whi + 6 * SS, Wlo + 6 * SS, S_);

    const int nA = T_ * B_ * E_;
    dim3 gproj((T_ * B_) / 128, S_ / 128);

    convA_k<<<(nA + 255) / 256, 256>>>(Xemb);
    tc_gemm<<<gproj, 256, smem_tc>>>(Ahi, Alo, Whi + 0 * SS, Wlo + 0 * SS, bz, Xz0, S_, 0);
    tc_gemm<<<gproj, 256, smem_tc>>>(Ahi, Alo, Whi + 1 * SS, Wlo + 1 * SS, br, Xr0, S_, 0);
    tc_gemm<<<gproj, 256, smem_tc>>>(Ahi, Alo, Whi + 2 * SS, Wlo + 2 * SS, bn, Xn0, S_, 0);

    gru_pass<<<NBLK, RT_, smem_rec>>>(Xz0, Xr0, Xn0, WhT, hb0, Xemb, 0u);

    convA_k<<<(nA + 255) / 256, 256>>>(Xemb);
    tc_gemm<<<gproj, 256, smem_tc>>>(Ahi, Alo, Whi + 3 * SS, Wlo + 3 * SS, bz + S_, Xz0, S_, 0);
    tc_gemm<<<gproj, 256, smem_tc>>>(Ahi, Alo, Whi + 4 * SS, Wlo + 4 * SS, br + S_, Xr0, S_, 0);
    tc_gemm<<<gproj, 256, smem_tc>>>(Ahi, Alo, Whi + 5 * SS, Wlo + 5 * SS, bn + S_, Xn0, S_, 0);

    gru_pass<<<NBLK, RT_, smem_rec>>>(Xz0, Xr0, Xn0, WhT + 3 * SS, hb1, H2, 2u * T_);

    convA_k<<<(nA + 255) / 256, 256>>>(H2);
    dim3 gout((T_ * B_) / 128, V_ / 128);
    tc_gemm<<<gout, 256, smem_tc>>>(Ahi, Alo, Whi + 6 * SS, Wlo + 6 * SS, bo, out, V_, 1);

    if (hout) copy_h_k<<<(B_ * S_ + 255) / 256, 256>>>(hout);
}

// round 14
// speedup vs baseline: 1.7336x; 1.0150x over previous
#include <cuda_runtime.h>
#include <cuda_bf16.h>
#include <math.h>
#include <stdint.h>

#define B_ 16
#define T_ 256
#define S_ 1024
#define E_ 1024
#define V_ 32000
#define NBLK 148
#define RT_ 384                       // recurrence block size
#define NC_ 16                        // K chunks of 64 (GEMM)
#define STAGE_BYTES 65536             // Ahi/Alo/Bhi/Blo, 16 KB each

typedef unsigned long long u64;

// ------------------ scratch (device globals; no allocation allowed) -------------
__device__ float g_Xemb[T_*B_*E_];      // embeddings; later reused as H1
__device__ float g_Xz0[T_*B_*S_];
__device__ float g_Xr0[T_*B_*S_];
__device__ float g_Xn0[T_*B_*S_];
__device__ float g_H2[T_*B_*S_];
__device__ float g_WhT[6*S_*S_];        // fp32 transposed hidden weights (recurrence)
__device__ float g_hb0[B_*S_];          // [b*S + c]
__device__ float g_hb1[B_*S_];
__device__ float g_zbuf[B_*S_];
__device__ float g_rhbuf[B_*S_];
__device__ unsigned int g_flags[256];
// bf16 split operands for tensor-core GEMMs
__device__ uint16_t g_Ahi[T_*B_*E_];
__device__ uint16_t g_Alo[T_*B_*E_];
__device__ uint16_t g_Whi[6*S_*S_ + V_*S_];
__device__ uint16_t g_Wlo[6*S_*S_ + V_*S_];

// ------------------ PTX helpers --------------------------------------------------
__device__ __forceinline__ uint32_t smem_u32(const void* p) {
    uint32_t a;
    asm("{ .reg .u64 t; cvta.to.shared.u64 t, %1; cvt.u32.u64 %0, t; }" : "=r"(a) : "l"(p));
    return a;
}
__device__ __forceinline__ void cpa16(uint32_t s, const void* g) {
    asm volatile("cp.async.cg.shared.global [%0], [%1], 16;" :: "r"(s), "l"(g));
}
__device__ __forceinline__ void cpa_commit() { asm volatile("cp.async.commit_group;"); }
template <int N> __device__ __forceinline__ void cpa_wait() {
    asm volatile("cp.async.wait_group %0;" :: "n"(N));
}
#define LDSM4(r0, r1, r2, r3, a) \
    asm volatile("ldmatrix.sync.aligned.m8n8.x4.shared.b16 {%0,%1,%2,%3}, [%4];" \
        : "=r"(r0), "=r"(r1), "=r"(r2), "=r"(r3) : "r"(a))
#define MMA16816(d, a, b) \
    asm volatile("mma.sync.aligned.m16n8k16.row.col.f32.bf16.bf16.f32 " \
        "{%0,%1,%2,%3}, {%4,%5,%6,%7}, {%8,%9}, {%0,%1,%2,%3};" \
        : "+f"((d)[0]), "+f"((d)[1]), "+f"((d)[2]), "+f"((d)[3]) \
        : "r"((a)[0]), "r"((a)[1]), "r"((a)[2]), "r"((a)[3]), "r"((b)[0]), "r"((b)[1]))

// packed f32x2 ops (baseline sm_100+, PTX-only)
__device__ __forceinline__ void fma2(u64& d, u64 a, u64 b) {
    asm("fma.rn.f32x2 %0, %1, %2, %0;" : "+l"(d) : "l"(a), "l"(b));
}
__device__ __forceinline__ u64 add2(u64 a, u64 b) {
    u64 r; asm("add.rn.f32x2 %0, %1, %2;" : "=l"(r) : "l"(a), "l"(b)); return r;
}
__device__ __forceinline__ u64 pack2(float x, float y) {
    u64 r; asm("mov.b64 %0, {%1, %2};" : "=l"(r) : "f"(x), "f"(y)); return r;
}
__device__ __forceinline__ float2 unpack2(u64 v) {
    float2 r; asm("mov.b64 {%0, %1}, %2;" : "=f"(r.x), "=f"(r.y) : "l"(v)); return r;
}
__device__ __forceinline__ u64 shfl64(u64 v, int off) {
    return __shfl_xor_sync(0xffffffffu, v, off);
}

// ------------------ small utility kernels ---------------------------------------
__global__ void reset_k() { if (threadIdx.x < 256) g_flags[threadIdx.x] = 0u; }

__global__ void embed_k(const int* __restrict__ x, const float* __restrict__ emb) {
    int idx = blockIdx.x * blockDim.x + threadIdx.x;
    const int total = T_ * B_ * (E_ / 4);
    const int stride = gridDim.x * blockDim.x;
    for (; idx < total; idx += stride) {
        int e4 = idx & (E_/4 - 1);
        int tb = idx >> 8;
        int t = tb >> 4, b = tb & 15;
        int tok = x[b * T_ + t];
        reinterpret_cast<float4*>(g_Xemb)[idx] =
            reinterpret_cast<const float4*>(emb)[(size_t)tok * (E_/4) + e4];
    }
}

// Tiled transpose for recurrence hidden weights: coalesced on BOTH sides.
// grid (S/32, S/32, 6): z = j*3+g. dst[c*S + k] = W_g[(j*(E+S)+E + k)*S + c]
__global__ void prepT_k(const float* __restrict__ Wz, const float* __restrict__ Wr,
                        const float* __restrict__ Wn) {
    __shared__ float smt[32][33];
    const int zc = blockIdx.z;
    const int j = zc / 3, g = zc - 3 * j;
    const float* W = ((g == 0) ? Wz : (g == 1) ? Wr : Wn)
                   + ((size_t)(j * (E_ + S_) + E_)) * S_;
    const int c0 = blockIdx.x * 32, k0 = blockIdx.y * 32;
    const int tx = threadIdx.x, ty = threadIdx.y;
    smt[ty][tx] = W[(size_t)(k0 + ty) * S_ + c0 + tx];      // coalesced read (c fast)
    __syncthreads();
    g_WhT[(size_t)zc * S_ * S_ + (size_t)(c0 + ty) * S_ + k0 + tx] = smt[tx][ty];  // coalesced write (k fast)
}

__global__ void convA_k(const float* __restrict__ src) {
    int i = blockIdx.x * blockDim.x + threadIdx.x;
    if (i < T_ * B_ * E_) {
        float x = src[i];
        __nv_bfloat16 h = __float2bfloat16(x);
        g_Ahi[i] = __bfloat16_as_ushort(h);
        g_Alo[i] = __bfloat16_as_ushort(__float2bfloat16(x - __bfloat162float(h)));
    }
}

__global__ void convW_k(const float* __restrict__ src, int ldn,
                        uint16_t* __restrict__ dhi, uint16_t* __restrict__ dlo, int K) {
    __shared__ float smt[32][33];
    int n0 = blockIdx.x * 32, k0 = blockIdx.y * 32;
    int tx = threadIdx.x, ty = threadIdx.y;
    smt[ty][tx] = src[(size_t)(k0 + ty) * ldn + n0 + tx];
    __syncthreads();
    float x = smt[tx][ty];
    __nv_bfloat16 h = __float2bfloat16(x);
    size_t o = (size_t)(n0 + ty) * K + k0 + tx;
    dhi[o] = __bfloat16_as_ushort(h);
    dlo[o] = __bfloat16_as_ushort(__float2bfloat16(x - __bfloat162float(h)));
}

// ------------------ mma.sync split-bf16 GEMM -------------------------------------
__device__ __forceinline__ uint32_t sw_addr(uint32_t base, int row, int chunk) {
    return base + row * 128 + (((chunk ^ (row & 7)) & 7) << 4);
}

__device__ __forceinline__ void load_chunk(
    uint32_t sb, const uint16_t* __restrict__ Ah, const uint16_t* __restrict__ Al,
    const uint16_t* __restrict__ Bh, const uint16_t* __restrict__ Bl,
    int m0, int n0, int c, int tid)
{
    const int ko = c * 64;
#pragma unroll
    for (int it = 0; it < 4; it++) {
        int o = tid + it * 256;
        int row = o >> 3, ch = o & 7;
        uint32_t dst = sw_addr(sb, row, ch);
        const size_t goffA = (size_t)(m0 + row) * 1024 + ko + ch * 8;
        const size_t goffB = (size_t)(n0 + row) * 1024 + ko + ch * 8;
        cpa16(dst,         Ah + goffA);
        cpa16(dst + 16384, Al + goffA);
        cpa16(dst + 32768, Bh + goffB);
        cpa16(dst + 49152, Bl + goffB);
    }
}

// Core GEMM body; gate weights/bias/output selectable (for fused 3-gate launch).
__device__ __forceinline__ void tc_gemm_body(
    const uint16_t* __restrict__ Ah, const uint16_t* __restrict__ Al,
    const uint16_t* __restrict__ Bh, const uint16_t* __restrict__ Bl,
    const float* __restrict__ bias, float* __restrict__ C, int Ntot, int remap)
{
    extern __shared__ char smem[];
    const uint32_t sbase = smem_u32(smem);
    const int tid = threadIdx.x;
    const int w = tid >> 5, lane = tid & 31;
    const int m0 = blockIdx.x * 128;
    const int n0 = blockIdx.y * 128;
    const int wm = (w & 1) * 64, wn = (w >> 1) * 32;

    float acc[4][4][4];
#pragma unroll
    for (int i = 0; i < 4; i++)
#pragma unroll
        for (int j = 0; j < 4; j++)
#pragma unroll
            for (int q = 0; q < 4; q++) acc[i][j][q] = 0.f;

    const int sub = lane >> 3, l7 = lane & 7;
    const int a_row_off = (sub & 1) * 8 + l7;
    const int a_ch_off  = sub >> 1;
    const int b_row_off = (sub >> 1) * 8 + l7;
    const int b_ch_off  = sub & 1;

    load_chunk(sbase, Ah, Al, Bh, Bl, m0, n0, 0, tid);
    cpa_commit();

    for (int c = 0; c < NC_; c++) {
        if (c + 1 < NC_) {
            load_chunk(sbase + ((c + 1) & 1) * STAGE_BYTES, Ah, Al, Bh, Bl, m0, n0, c + 1, tid);
            cpa_commit();
            cpa_wait<1>();
        } else {
            cpa_wait<0>();
        }
        __syncthreads();

        const uint32_t sAh = sbase + (c & 1) * STAGE_BYTES;
        const uint32_t sAl = sAh + 16384;
        const uint32_t sBh = sAh + 32768;
        const uint32_t sBl = sAh + 49152;

#pragma unroll
        for (int kk = 0; kk < 4; kk++) {
            uint32_t Afh[4][4], Afl[4][4], Bfh[4][2], Bfl[4][2];
#pragma unroll
            for (int mt = 0; mt < 4; mt++) {
                int row = wm + mt * 16 + a_row_off;
                int ch = kk * 2 + a_ch_off;
                LDSM4(Afh[mt][0], Afh[mt][1], Afh[mt][2], Afh[mt][3], sw_addr(sAh, row, ch));
                LDSM4(Afl[mt][0], Afl[mt][1], Afl[mt][2], Afl[mt][3], sw_addr(sAl, row, ch));
            }
#pragma unroll
            for (int pr = 0; pr < 2; pr++) {
                int row = wn + pr * 16 + b_row_off;
                int ch = kk * 2 + b_ch_off;
                LDSM4(Bfh[2*pr][0], Bfh[2*pr][1], Bfh[2*pr+1][0], Bfh[2*pr+1][1],
                      sw_addr(sBh, row, ch));
                LDSM4(Bfl[2*pr][0], Bfl[2*pr][1], Bfl[2*pr+1][0], Bfl[2*pr+1][1],
                      sw_addr(sBl, row, ch));
            }
#pragma unroll
            for (int mt = 0; mt < 4; mt++)
#pragma unroll
                for (int nt = 0; nt < 4; nt++) {
                    MMA16816(acc[mt][nt], Afh[mt], Bfh[nt]);
                    MMA16816(acc[mt][nt], Afh[mt], Bfl[nt]);
                    MMA16816(acc[mt][nt], Afl[mt], Bfh[nt]);
                }
        }
        __syncthreads();
    }

    const int er = lane >> 2, ec = (lane & 3) * 2;
#pragma unroll
    for (int mt = 0; mt < 4; mt++) {
#pragma unroll
        for (int nt = 0; nt < 4; nt++) {
            int col = n0 + wn + nt * 8 + ec;
            float b0 = bias[col], b1 = bias[col + 1];
            int m1 = m0 + wm + mt * 16 + er;
            int m2 = m1 + 8;
            int r1 = remap ? ((m1 & 15) * T_ + (m1 >> 4)) : m1;
            int r2 = remap ? ((m2 & 15) * T_ + (m2 >> 4)) : m2;
            float2 v1 = make_float2(acc[mt][nt][0] + b0, acc[mt][nt][1] + b1);
            float2 v2 = make_float2(acc[mt][nt][2] + b0, acc[mt][nt][3] + b1);
            *reinterpret_cast<float2*>(C + (size_t)r1 * Ntot + col) = v1;
            *reinterpret_cast<float2*>(C + (size_t)r2 * Ntot + col) = v2;
        }
    }
}

__global__ __launch_bounds__(256, 1) void tc_gemm(
    const uint16_t* __restrict__ Ah, const uint16_t* __restrict__ Al,
    const uint16_t* __restrict__ Bh, const uint16_t* __restrict__ Bl,
    const float* __restrict__ bias, float* __restrict__ C, int Ntot, int remap)
{
    tc_gemm_body(Ah, Al, Bh, Bl, bias, C, Ntot, remap);
}

// Fused 3-gate projection: blockIdx.z selects gate (weights offset, bias, output).
__global__ __launch_bounds__(256, 1) void tc_gemm3(
    const uint16_t* __restrict__ Ah, const uint16_t* __restrict__ Al,
    const uint16_t* __restrict__ Whb_hi, const uint16_t* __restrict__ Whb_lo,
    const float* __restrict__ bz, const float* __restrict__ br, const float* __restrict__ bn,
    float* __restrict__ Cz, float* __restrict__ Cr, float* __restrict__ Cn,
    int bias_off)
{
    const int g = blockIdx.z;
    const size_t SS = (size_t)S_ * S_;
    const uint16_t* Bh = Whb_hi + (size_t)g * SS;
    const uint16_t* Bl = Whb_lo + (size_t)g * SS;
    const float* bias = ((g == 0) ? bz : (g == 1) ? br : bn) + bias_off;
    float* C = (g == 0) ? Cz : (g == 1) ? Cr : Cn;
    tc_gemm_body(Ah, Al, Bh, Bl, bias, C, S_, 0);
}

// ------------------ persistent single-layer recurrence ---------------------------
__device__ __forceinline__ void flag_barrier(unsigned int e) {
    __syncthreads();
    if (threadIdx.x == 0) {
        __threadfence();
        *((volatile unsigned int*)&g_flags[blockIdx.x]) = e;
    }
    if (threadIdx.x < 32) {
        const int lane = threadIdx.x;
        for (;;) {
            bool ok = true;
            for (int i = lane; i < (int)gridDim.x; i += 32)
                ok &= (*((volatile const unsigned int*)&g_flags[i]) >= e);
            if (__all_sync(0xffffffffu, ok)) break;
            __nanosleep(20);
        }
        __threadfence();
    }
    __syncthreads();
}

__device__ __forceinline__ void load_sh(float* dst, const float* src, int tid) {
    const float4* s4 = reinterpret_cast<const float4*>(src);
    float4* d4 = reinterpret_cast<float4*>(dst);
#pragma unroll
    for (int i = tid; i < B_ * S_ / 4; i += RT_) d4[i] = __ldcg(s4 + i);
}

// Dual dot over b-major smem h: acc[0..15] vs w0, acc[16..31] vs w1, 16 batches.
// Each u64 acc holds (even-k partial, odd-k partial); caller sums .x+.y at the end.
__device__ __forceinline__ void dual_dot2(const float* __restrict__ w0row,
                                          const float* __restrict__ w1row,
                                          const float* __restrict__ sh,
                                          int lane, u64 acc[32]) {
    const float4* w04 = reinterpret_cast<const float4*>(w0row);
    const float4* w14 = reinterpret_cast<const float4*>(w1row);
#pragma unroll
    for (int kk = 0; kk < 8; kk++) {
        float4 a = w04[kk * 32 + lane];
        float4 b = w14[kk * 32 + lane];
        u64 a_lo = pack2(a.x, a.y), a_hi = pack2(a.z, a.w);
        u64 b_lo = pack2(b.x, b.y), b_hi = pack2(b.z, b.w);
        int kb = (kk * 32 + lane) * 4;
#pragma unroll
        for (int bb = 0; bb < 16; bb++) {
            ulonglong2 h2 = *reinterpret_cast<const ulonglong2*>(sh + bb * S_ + kb);
            fma2(acc[bb],      a_lo, h2.x);
            fma2(acc[bb],      a_hi, h2.y);
            fma2(acc[16 + bb], b_lo, h2.x);
            fma2(acc[16 + bb], b_hi, h2.y);
        }
    }
}

// Folding butterfly over 32 packed entries; lane l ends with entry l (pairs intact).
__device__ __forceinline__ u64 reduce32p(u64 acc[32], int lane) {
    int cnt = 32;
#pragma unroll
    for (int off = 16; off >= 1; off >>= 1) {
        const bool up = (lane & off) != 0;
        const int half = cnt >> 1;
#pragma unroll
        for (int i = 0; i < 16; i++) {
            if (i < half) {
                u64 send = up ? acc[i] : acc[i + half];
                u64 recv = shfl64(send, off);
                acc[i] = add2(up ? acc[i + half] : acc[i], recv);
            }
        }
        cnt = half;
    }
    return acc[0];
}

__global__ __launch_bounds__(RT_, 1) void gru_pass(
    const float* __restrict__ Xz, const float* __restrict__ Xr,
    const float* __restrict__ Xn, const float* __restrict__ WhT,
    float* __restrict__ hbuf, float* __restrict__ Hseq, unsigned int ebase)
{
    extern __shared__ float sh[];
    float* shA = sh;              // h   [b*S + k]
    float* shB = sh + B_ * S_;    // r*h [b*S + k]
    const int tid = threadIdx.x;
    const int lane = tid & 31;
    const int wib = tid >> 5;
    const int bid = blockIdx.x;
    const int pA = wib * NBLK + bid;

    for (int i = tid; i < B_ * S_; i += RT_) shA[i] = 0.f;
    __syncthreads();

    for (int t = 0; t < T_; ++t) {
        // ---- stage A: z and r at column pA ----
        if (pA < S_) {
            const float* w0 = WhT + ((size_t)0 * S_ + pA) * S_;   // Whz row
            const float* w1 = WhT + ((size_t)1 * S_ + pA) * S_;   // Whr row
            u64 acc[32];
#pragma unroll
            for (int i = 0; i < 32; i++) acc[i] = 0ull;
            dual_dot2(w0, w1, shA, lane, acc);
            float2 sv = unpack2(reduce32p(acc, lane));
            float s = sv.x + sv.y;
            int b = lane & 15;
            const float* Xg = (lane < 16) ? Xz : Xr;
            float pre = Xg[((size_t)t * B_ + b) * S_ + pA] + s;
            float sg = 1.f / (1.f + __expf(-pre));
            if (lane < 16) __stcg(&g_zbuf[b * S_ + pA], sg);
            else           __stcg(&g_rhbuf[b * S_ + pA], sg * shA[b * S_ + pA]);
        }
        flag_barrier(ebase + 2 * t + 1);
        load_sh(shB, g_rhbuf, tid);
        __syncthreads();

        // ---- stage B: n at columns 2pA, 2pA+1; h update ----
        if (pA < S_ / 2) {
            const int c0 = 2 * pA;
            const float* w0 = WhT + ((size_t)2 * S_ + c0) * S_;       // Whn rows
            const float* w1 = WhT + ((size_t)2 * S_ + c0 + 1) * S_;
            u64 acc[32];
#pragma unroll
            for (int i = 0; i < 32; i++) acc[i] = 0ull;
            dual_dot2(w0, w1, shB, lane, acc);
            float2 sv = unpack2(reduce32p(acc, lane));
            float s = sv.x + sv.y;
            int b = lane & 15;
            int col = c0 + (lane >> 4);
            float pre = Xn[((size_t)t * B_ + b) * S_ + col] + s;
            float n = tanhf(pre);
            float ho = shA[b * S_ + col];
            float z  = __ldcg(&g_zbuf[b * S_ + col]);
            float hn = ho + z * (n - ho);
            __stcg(&hbuf[b * S_ + col], hn);
            __stcg(&Hseq[((size_t)t * B_ + b) * S_ + col], hn);
        }
        flag_barrier(ebase + 2 * t + 2);
        load_sh(shA, hbuf, tid);
        __syncthreads();
    }
}

__global__ void copy_h_k(float* __restrict__ hout) {
    int i = blockIdx.x * blockDim.x + threadIdx.x;
    if (i < B_ * S_) {
        hout[i]           = g_hb0[i];
        hout[B_ * S_ + i] = g_hb1[i];
    }
}

// ------------------ launch --------------------------------------------------------
extern "C" void kernel_launch(void* const* d_in, const int* in_sizes, int n_in,
                              void* d_out, int out_size) {
    const int*   x   = (const int*)  d_in[0];
    const float* emb = (const float*)d_in[1];
    const float* Wz  = (const float*)d_in[2];
    const float* bz  = (const float*)d_in[3];
    const float* Wr  = (const float*)d_in[4];
    const float* br  = (const float*)d_in[5];
    const float* Wn  = (const float*)d_in[6];
    const float* bn  = (const float*)d_in[7];
    const float* Wo  = (const float*)d_in[8];
    const float* bo  = (const float*)d_in[9];
    float* out = (float*)d_out;
    (void)in_sizes; (void)n_in;

    const int smem_rec = 2 * B_ * S_ * (int)sizeof(float);     // 128 KB
    const int smem_tc  = 2 * STAGE_BYTES;                       // 128 KB
    cudaFuncSetAttribute(gru_pass, cudaFuncAttributeMaxDynamicSharedMemorySize, smem_rec);
    cudaFuncSetAttribute(tc_gemm,  cudaFuncAttributeMaxDynamicSharedMemorySize, smem_tc);
    cudaFuncSetAttribute(tc_gemm3, cudaFuncAttributeMaxDynamicSharedMemorySize, smem_tc);

    float *Xemb, *Xz0, *Xr0, *Xn0, *H2, *WhT, *hb0, *hb1;
    uint16_t *Ahi, *Alo, *Whi, *Wlo;
    cudaGetSymbolAddress((void**)&Xemb, g_Xemb);
    cudaGetSymbolAddress((void**)&Xz0, g_Xz0);
    cudaGetSymbolAddress((void**)&Xr0, g_Xr0);
    cudaGetSymbolAddress((void**)&Xn0, g_Xn0);
    cudaGetSymbolAddress((void**)&H2,  g_H2);
    cudaGetSymbolAddress((void**)&WhT, g_WhT);
    cudaGetSymbolAddress((void**)&hb0, g_hb0);
    cudaGetSymbolAddress((void**)&hb1, g_hb1);
    cudaGetSymbolAddress((void**)&Ahi, g_Ahi);
    cudaGetSymbolAddress((void**)&Alo, g_Alo);
    cudaGetSymbolAddress((void**)&Whi, g_Whi);
    cudaGetSymbolAddress((void**)&Wlo, g_Wlo);

    float* hout = nullptr;
    long long need = (long long)B_ * T_ * V_ + 2LL * B_ * S_;
    if ((long long)out_size >= need) hout = out + (size_t)B_ * T_ * V_;

    const size_t SS = (size_t)S_ * S_;

    reset_k<<<1, 256>>>();
    embed_k<<<1024, 256>>>(x, emb);

    // recurrence hidden-weight transpose: tiled, coalesced both sides
    {
        dim3 tb(32, 32);
        dim3 tg(S_ / 32, S_ / 32, 6);
        prepT_k<<<tg, tb>>>(Wz, Wr, Wn);
    }

    // bf16 hi/lo weight conversions: 6 gate input-weights [S,S] + Wo [S,V]
    dim3 cb(32, 32);
    dim3 cgGate(S_ / 32, S_ / 32);
    convW_k<<<cgGate, cb>>>(Wz,                          S_, Whi + 0 * SS, Wlo + 0 * SS, S_);
    convW_k<<<cgGate, cb>>>(Wr,                          S_, Whi + 1 * SS, Wlo + 1 * SS, S_);
    convW_k<<<cgGate, cb>>>(Wn,                          S_, Whi + 2 * SS, Wlo + 2 * SS, S_);
    convW_k<<<cgGate, cb>>>(Wz + (size_t)(E_ + S_) * S_, S_, Whi + 3 * SS, Wlo + 3 * SS, S_);
    convW_k<<<cgGate, cb>>>(Wr + (size_t)(E_ + S_) * S_, S_, Whi + 4 * SS, Wlo + 4 * SS, S_);
    convW_k<<<cgGate, cb>>>(Wn + (size_t)(E_ + S_) * S_, S_, Whi + 5 * SS, Wlo + 5 * SS, S_);
    dim3 cgVoc(V_ / 32, S_ / 32);
    convW_k<<<cgVoc, cb>>>(Wo, V_, Whi + 6 * SS, Wlo + 6 * SS, S_);

    const int nA = T_ * B_ * E_;
    dim3 gproj3((T_ * B_) / 128, S_ / 128, 3);   // fused 3-gate projection

    // layer-0 input projections (fused single launch)
    convA_k<<<(nA + 255) / 256, 256>>>(Xemb);
    tc_gemm3<<<gproj3, 256, smem_tc>>>(Ahi, Alo, Whi + 0 * SS, Wlo + 0 * SS,
                                       bz, br, bn, Xz0, Xr0, Xn0, 0);

    gru_pass<<<NBLK, RT_, smem_rec>>>(Xz0, Xr0, Xn0, WhT, hb0, Xemb, 0u);

    // layer-1 input projections (fused single launch)
    convA_k<<<(nA + 255) / 256, 256>>>(Xemb);
    tc_gemm3<<<gproj3, 256, smem_tc>>>(Ahi, Alo, Whi + 3 * SS, Wlo + 3 * SS,
                                       bz, br, bn, Xz0, Xr0, Xn0, S_);

    gru_pass<<<NBLK, RT_, smem_rec>>>(Xz0, Xr0, Xn0, WhT + 3 * SS, hb1, H2, 2u * T_);

    // vocab projection, rows remapped to [B, T, V]
    convA_k<<<(nA + 255) / 256, 256>>>(H2);
    dim3 gout((T_ * B_) / 128, V_ / 128);
    tc_gemm<<<gout, 256, smem_tc>>>(Ahi, Alo, Whi + 6 * SS, Wlo + 6 * SS, bo, out, V_, 1);

    if (hout) copy_h_k<<<(B_ * S_ + 255) / 256, 256>>>(hout);
}